// round 15
// baseline (speedup 1.0000x reference)
#include <cuda_runtime.h>
#include <cuda_fp16.h>
#include <math_constants.h>
#include <cstdint>

#define BATCH  2
#define SEQ    2048
#define DMODEL 1024
#define NHEADS 16
#define HDIM   64
#define MTOT   (BATCH*SEQ)   // 4096
#define WSZ    (DMODEL*DMODEL)

// ---------------- scratch (allocation-free rule: __device__ globals) --------
__device__ __half g_X[(size_t)MTOT * DMODEL];
__device__ __half g_W[(size_t)4 * WSZ];
__device__ __half g_Q[(size_t)MTOT * DMODEL];
__device__ __half g_K[(size_t)MTOT * DMODEL];
__device__ __half g_V[(size_t)MTOT * DMODEL];
__device__ __half g_C[(size_t)MTOT * DMODEL];

// ---------------- helpers (baseline ISA only) --------------------------------
__device__ __forceinline__ uint32_t smem_u32(const void* p) {
    uint32_t a;
    asm("{ .reg .u64 t; cvta.to.shared.u64 t, %1; cvt.u32.u64 %0, t; }"
        : "=r"(a) : "l"(p));
    return a;
}
__device__ __forceinline__ void cpasync16(uint32_t dst, const void* src) {
    asm volatile("cp.async.cg.shared.global [%0], [%1], 16;" :: "r"(dst), "l"(src));
}
#define CPASYNC_COMMIT() asm volatile("cp.async.commit_group;" ::: "memory")
#define CPASYNC_WAIT(n)  asm volatile("cp.async.wait_group %0;" :: "n"(n) : "memory")

__device__ __forceinline__ void ldm_x4(uint32_t* r, uint32_t addr) {
    asm volatile("ldmatrix.sync.aligned.m8n8.x4.shared.b16 {%0,%1,%2,%3}, [%4];"
        : "=r"(r[0]), "=r"(r[1]), "=r"(r[2]), "=r"(r[3]) : "r"(addr));
}
__device__ __forceinline__ void ldm_x4t(uint32_t* r, uint32_t addr) {
    asm volatile("ldmatrix.sync.aligned.m8n8.x4.trans.shared.b16 {%0,%1,%2,%3}, [%4];"
        : "=r"(r[0]), "=r"(r[1]), "=r"(r[2]), "=r"(r[3]) : "r"(addr));
}
// fp32-accumulator MMA
__device__ __forceinline__ void mma_f16(float* c, const uint32_t* a,
                                        uint32_t b0, uint32_t b1) {
    asm volatile("mma.sync.aligned.m16n8k16.row.col.f32.f16.f16.f32 "
        "{%0,%1,%2,%3}, {%4,%5,%6,%7}, {%8,%9}, {%0,%1,%2,%3};"
        : "+f"(c[0]), "+f"(c[1]), "+f"(c[2]), "+f"(c[3])
        : "r"(a[0]), "r"(a[1]), "r"(a[2]), "r"(a[3]), "r"(b0), "r"(b1));
}
// fp16-accumulator MMA (2x issue rate) — used ONLY for S = QK^T
__device__ __forceinline__ void mma_f16h(uint32_t* c, const uint32_t* a,
                                         uint32_t b0, uint32_t b1) {
    asm volatile("mma.sync.aligned.m16n8k16.row.col.f16.f16.f16.f16 "
        "{%0,%1}, {%2,%3,%4,%5}, {%6,%7}, {%0,%1};"
        : "+r"(c[0]), "+r"(c[1])
        : "r"(a[0]), "r"(a[1]), "r"(a[2]), "r"(a[3]), "r"(b0), "r"(b1));
}
__device__ __forceinline__ uint32_t pack2h(float v0, float v1) {
    __half h0 = __float2half_rn(v0), h1 = __float2half_rn(v1);
    return ((uint32_t)__half_as_ushort(h1) << 16) | __half_as_ushort(h0);
}

// ---------------- fused fp32 -> fp16 convert (x + 4 weights) -----------------
#define XN8  (MTOT * DMODEL / 8)          // 524288
#define WN8  (WSZ / 8)                    // 131072
__global__ __launch_bounds__(256)
void split_all(const float* __restrict__ x,  const float* __restrict__ Wq,
               const float* __restrict__ Wk, const float* __restrict__ Wv,
               const float* __restrict__ Wo)
{
    int id = blockIdx.x * 256 + threadIdx.x;
    const float* src;
    __half* dst;
    int off;
    if (id < XN8) {
        src = x; dst = g_X; off = id;
    } else {
        int r = (id - XN8) >> 17;          // WN8 = 2^17
        off   = (id - XN8) & (WN8 - 1);
        src = (r == 0) ? Wq : (r == 1) ? Wk : (r == 2) ? Wv : Wo;
        dst = g_W + (size_t)r * WSZ;
    }
    const float4* s = (const float4*)src + (size_t)off * 2;
    float4 a = s[0], b = s[1];
    uint4 hp;
    hp.x = pack2h(a.x, a.y);
    hp.y = pack2h(a.z, a.w);
    hp.z = pack2h(b.x, b.y);
    hp.w = pack2h(b.z, b.w);
    ((uint4*)dst)[off] = hp;
}

// ---------------- HMMA GEMM (R13 config: 256 thr, warp 64x32, BK=64) --------
#define BK        64
#define ROWB      144                      // 128B data + 16B pad (conflict-free)
#define TILE_B    (128 * ROWB)             // 18432
#define OFF_B     (TILE_B)
#define STAGE_B   (2 * TILE_B)             // 36864
#define SMEM_GEMM (2 * STAGE_B)            // 73728

__device__ __forceinline__ void load_chunk(
    uint32_t sdst, const __half* __restrict__ A, const __half* __restrict__ W,
    int bm, int bn, int k0, int tid)
{
    #pragma unroll
    for (int it = 0; it < 4; it++) {
        int u = tid + it * 256;            // 0..1023: 128 rows x 8 x 16B
        int r = u >> 3, c = u & 7;
        uint32_t so = (uint32_t)(r * ROWB + c * 16);
        cpasync16(sdst + so,         A + (size_t)(bm + r) * DMODEL + k0 + c * 8);
        cpasync16(sdst + OFF_B + so, W + (size_t)(bn + r) * DMODEL + k0 + c * 8);
    }
}

__device__ __forceinline__ void gemm_hmma_body(
    const __half* __restrict__ A, const __half* __restrict__ W,
    const float* __restrict__ bias, int outmode,
    float* __restrict__ Y, __half* __restrict__ Yh)
{
    extern __shared__ char smem[];
    const uint32_t sb = smem_u32(smem);
    const int tid  = threadIdx.x;
    const int lane = tid & 31;
    const int wid  = tid >> 5;
    const int wm   = wid & 1;
    const int wn   = wid >> 1;

    const int bm = blockIdx.y * 128;
    const int bn = blockIdx.x * 128;

    float acc[4][4][4];
    #pragma unroll
    for (int mi = 0; mi < 4; mi++)
        #pragma unroll
        for (int ni = 0; ni < 4; ni++)
            #pragma unroll
            for (int e = 0; e < 4; e++) acc[mi][ni][e] = 0.f;

    const uint32_t a_row  = (uint32_t)(wm * 64 + (lane & 15));
    const uint32_t a_koff = (uint32_t)(((lane >> 4) & 1) * 16);
    const uint32_t b_nrow = (uint32_t)(wn * 32 + (lane & 7) + ((lane >> 4) & 1) * 8);
    const uint32_t b_koff = (uint32_t)(((lane >> 3) & 1) * 16);

    load_chunk(sb, A, W, bm, bn, 0, tid);
    CPASYNC_COMMIT();

    const int NCH = DMODEL / BK;           // 16
    for (int ch = 0; ch < NCH; ch++) {
        const uint32_t st = sb + (uint32_t)(ch & 1) * STAGE_B;
        if (ch + 1 < NCH) {
            load_chunk(sb + (uint32_t)((ch + 1) & 1) * STAGE_B,
                       A, W, bm, bn, (ch + 1) * BK, tid);
            CPASYNC_COMMIT();
            CPASYNC_WAIT(1);
        } else {
            CPASYNC_WAIT(0);
        }
        __syncthreads();

        #pragma unroll
        for (int ks = 0; ks < 4; ks++) {   // 4 x k16 per chunk
            const uint32_t kb = (uint32_t)(ks * 32);
            uint32_t aA[4][4], bB[2][4];
            #pragma unroll
            for (int mi = 0; mi < 4; mi++)
                ldm_x4(aA[mi], st + (a_row + mi * 16) * ROWB + kb + a_koff);
            #pragma unroll
            for (int p = 0; p < 2; p++)
                ldm_x4(bB[p], st + OFF_B + (b_nrow + p * 16) * ROWB + kb + b_koff);
            #pragma unroll
            for (int mi = 0; mi < 4; mi++)
                #pragma unroll
                for (int ni = 0; ni < 4; ni++) {
                    const uint32_t* bb = &bB[ni >> 1][(ni & 1) * 2];
                    mma_f16(acc[mi][ni], aA[mi], bb[0], bb[1]);
                }
        }
        __syncthreads();
    }

    const int l4 = lane >> 2;
    const int l2 = (lane & 3) * 2;
    #pragma unroll
    for (int mi = 0; mi < 4; mi++) {
        #pragma unroll
        for (int ni = 0; ni < 4; ni++) {
            int gr = bm + wm * 64 + mi * 16 + l4;
            int gc = bn + wn * 32 + ni * 8 + l2;
            float b0 = bias[gc], b1 = bias[gc + 1];
            float v0 = acc[mi][ni][0] + b0, v1 = acc[mi][ni][1] + b1;
            float v2 = acc[mi][ni][2] + b0, v3 = acc[mi][ni][3] + b1;
            if (outmode == 0) {
                *(float2*)(Y + (size_t)gr * DMODEL + gc)       = make_float2(v0, v1);
                *(float2*)(Y + (size_t)(gr + 8) * DMODEL + gc) = make_float2(v2, v3);
            } else {
                *(uint32_t*)(Yh + (size_t)gr * DMODEL + gc)       = pack2h(v0, v1);
                *(uint32_t*)(Yh + (size_t)(gr + 8) * DMODEL + gc) = pack2h(v2, v3);
            }
        }
    }
}

__global__ __launch_bounds__(256, 2)
void gemm_qkv_mma(const float* __restrict__ bq, const float* __restrict__ bk,
                  const float* __restrict__ bv)
{
    int z = blockIdx.z;
    const float* bias = (z == 0) ? bq : (z == 1) ? bk : bv;
    __half* Yh = (z == 0) ? g_Q : (z == 1) ? g_K : g_V;
    gemm_hmma_body(g_X, g_W + (size_t)z * WSZ, bias, 2, nullptr, Yh);
}

__global__ __launch_bounds__(256, 2)
void gemm_out_mma(const float* __restrict__ bo, float* __restrict__ Y)
{
    gemm_hmma_body(g_C, g_W + (size_t)3 * WSZ, bo, 0, Y, nullptr);
}

// ---------------- flash attention: S in fp16-acc MMA (2x rate) ---------------
#define FROWB   144                        // 64 fp16 = 128B + 16B pad
#define FQTILE  (128 * FROWB)              // 18432
#define KTILE   (64 * FROWB)               // 9216
#define KVSTAGE (2 * KTILE)                // 18432
#define FK      0
#define FV      (KTILE)
#define SMEM_FLASH (FQTILE + 3 * KVSTAGE)  // 73728 (72 KB)

__device__ __forceinline__ void flash_load_q(uint32_t sb, const __half* Qs,
                                             int q0, int tid)
{
    #pragma unroll
    for (int it = 0; it < 4; it++) {
        int u = tid + it * 256;           // 0..1023
        int r = u >> 3, c = u & 7;
        uint32_t so = (uint32_t)(r * FROWB + c * 16);
        cpasync16(sb + so, Qs + (size_t)(q0 + r) * DMODEL + c * 8);
    }
}
__device__ __forceinline__ void flash_load_kv(uint32_t stb,
    const __half* Ks, const __half* Vs, int k0, int tid)
{
    #pragma unroll
    for (int it = 0; it < 2; it++) {
        int u = tid + it * 256;           // 0..511
        int r = u >> 3, c = u & 7;
        uint32_t so = (uint32_t)(r * FROWB + c * 16);
        size_t ge = (size_t)(k0 + r) * DMODEL + c * 8;
        cpasync16(stb + FK + so, Ks + ge);
        cpasync16(stb + FV + so, Vs + ge);
    }
}

__global__ __launch_bounds__(256, 2)
void flash_attn_mma()
{
    extern __shared__ char smem[];
    const uint32_t sb = smem_u32(smem);
    const uint32_t kvb = sb + FQTILE;
    const int tid  = threadIdx.x;
    const int w    = tid >> 5;
    const int lane = tid & 31;

    const int b  = blockIdx.z;
    const int h  = blockIdx.y;
    const int q0 = blockIdx.x * 128;

    const size_t base = (size_t)b * SEQ * DMODEL + (size_t)h * HDIM;
    const __half* Qs = g_Q + base;
    const __half* Ks = g_K + base;
    const __half* Vs = g_V + base;

    const uint32_t qa = (uint32_t)((w * 16 + (lane & 15)) * FROWB
                      + ((lane >> 4) & 1) * 16);
    const uint32_t ka_row = (uint32_t)((lane & 7) + ((lane >> 4) & 1) * 8);
    const uint32_t ka_ko  = (uint32_t)(((lane >> 3) & 1) * 16);
    const uint32_t va_row = (uint32_t)(lane & 15);
    const uint32_t va_co  = (uint32_t)(((lane >> 4) & 1) * 16);

    float o[8][4];
    #pragma unroll
    for (int nb = 0; nb < 8; nb++)
        #pragma unroll
        for (int e = 0; e < 4; e++) o[nb][e] = 0.f;
    float m_a = -CUDART_INF_F, m_b = -CUDART_INF_F, l_a = 0.f, l_b = 0.f;

    uint32_t aQ[4][4];

    flash_load_q(sb, Qs, q0, tid);
    flash_load_kv(kvb, Ks, Vs, 0, tid);
    CPASYNC_COMMIT();
    flash_load_kv(kvb + KVSTAGE, Ks, Vs, 64, tid);
    CPASYNC_COMMIT();

    const int NKT = SEQ / 64;             // 32
    uint32_t stage = 0;
    for (int kt = 0; kt < NKT; kt++) {
        if (kt == NKT - 1) { CPASYNC_WAIT(0); } else { CPASYNC_WAIT(1); }
        __syncthreads();

        if (kt + 2 < NKT) {
            uint32_t s2 = stage + 2 * KVSTAGE;
            if (s2 >= 3 * KVSTAGE) s2 -= 3 * KVSTAGE;
            flash_load_kv(kvb + s2, Ks, Vs, (kt + 2) * 64, tid);
            CPASYNC_COMMIT();
        }

        const uint32_t st = kvb + stage;

        if (kt == 0) {
            #pragma unroll
            for (int k4 = 0; k4 < 4; k4++)
                ldm_x4(aQ[k4], sb + qa + k4 * 32);
        }

        // ---- S = Q K^T : fp16 accumulators (2x issue rate) -------------------
        uint32_t sf[8][2];
        #pragma unroll
        for (int j = 0; j < 8; j++) { sf[j][0] = 0u; sf[j][1] = 0u; }

        #pragma unroll
        for (int k4 = 0; k4 < 4; k4++) {
            uint32_t kS[4][4];
            #pragma unroll
            for (int nb = 0; nb < 4; nb++)
                ldm_x4(kS[nb], st + FK + (uint32_t)(nb * 16) * FROWB
                               + ka_row * FROWB + ka_ko + k4 * 32);
            #pragma unroll
            for (int nb = 0; nb < 4; nb++) {
                mma_f16h(sf[2*nb],   aQ[k4], kS[nb][0], kS[nb][1]);
                mma_f16h(sf[2*nb+1], aQ[k4], kS[nb][2], kS[nb][3]);
            }
        }

        // unpack fp16 S fragments -> fp32 (same layout as before)
        float s[8][4];
        #pragma unroll
        for (int j = 0; j < 8; j++) {
            float2 lo = __half22float2(*(__half2*)&sf[j][0]);
            float2 hi = __half22float2(*(__half2*)&sf[j][1]);
            s[j][0] = lo.x; s[j][1] = lo.y;
            s[j][2] = hi.x; s[j][3] = hi.y;
        }

        // ---- online softmax (rows a = lane/4, b = lane/4+8) -----------------
        float mloc_a = -CUDART_INF_F, mloc_b = -CUDART_INF_F;
        #pragma unroll
        for (int j = 0; j < 8; j++) {
            s[j][0] *= 0.125f; s[j][1] *= 0.125f;
            s[j][2] *= 0.125f; s[j][3] *= 0.125f;
            mloc_a = fmaxf(mloc_a, fmaxf(s[j][0], s[j][1]));
            mloc_b = fmaxf(mloc_b, fmaxf(s[j][2], s[j][3]));
        }
        mloc_a = fmaxf(mloc_a, __shfl_xor_sync(0xffffffffu, mloc_a, 1));
        mloc_a = fmaxf(mloc_a, __shfl_xor_sync(0xffffffffu, mloc_a, 2));
        mloc_b = fmaxf(mloc_b, __shfl_xor_sync(0xffffffffu, mloc_b, 1));
        mloc_b = fmaxf(mloc_b, __shfl_xor_sync(0xffffffffu, mloc_b, 2));

        float mn_a = fmaxf(m_a, mloc_a), mn_b = fmaxf(m_b, mloc_b);
        float corr_a = __expf(m_a - mn_a), corr_b = __expf(m_b - mn_b);
        m_a = mn_a; m_b = mn_b;

        float rs_a = 0.f, rs_b = 0.f;
        #pragma unroll
        for (int j = 0; j < 8; j++) {
            s[j][0] = __expf(s[j][0] - mn_a);
            s[j][1] = __expf(s[j][1] - mn_a);
            s[j][2] = __expf(s[j][2] - mn_b);
            s[j][3] = __expf(s[j][3] - mn_b);
            rs_a += s[j][0] + s[j][1];
            rs_b += s[j][2] + s[j][3];
        }
        rs_a += __shfl_xor_sync(0xffffffffu, rs_a, 1);
        rs_a += __shfl_xor_sync(0xffffffffu, rs_a, 2);
        rs_b += __shfl_xor_sync(0xffffffffu, rs_b, 1);
        rs_b += __shfl_xor_sync(0xffffffffu, rs_b, 2);
        l_a = l_a * corr_a + rs_a;
        l_b = l_b * corr_b + rs_b;

        #pragma unroll
        for (int nb = 0; nb < 8; nb++) {
            o[nb][0] *= corr_a; o[nb][1] *= corr_a;
            o[nb][2] *= corr_b; o[nb][3] *= corr_b;
        }

        // ---- O += P V: fp32 acc (precision-critical) ------------------------
        #pragma unroll
        for (int t = 0; t < 4; t++) {
            uint32_t pP[4];
            pP[0] = pack2h(s[2*t][0],   s[2*t][1]);
            pP[1] = pack2h(s[2*t][2],   s[2*t][3]);
            pP[2] = pack2h(s[2*t+1][0], s[2*t+1][1]);
            pP[3] = pack2h(s[2*t+1][2], s[2*t+1][3]);

            uint32_t vS[4][4];
            #pragma unroll
            for (int ng = 0; ng < 4; ng++)
                ldm_x4t(vS[ng], st + FV + (uint32_t)(t * 16 + va_row) * FROWB
                                + (uint32_t)(ng * 32) + va_co);
            #pragma unroll
            for (int ng = 0; ng < 4; ng++) {
                mma_f16(o[2*ng],   pP, vS[ng][0], vS[ng][1]);
                mma_f16(o[2*ng+1], pP, vS[ng][2], vS[ng][3]);
            }
        }
        stage += KVSTAGE;
        if (stage >= 3 * KVSTAGE) stage = 0;
    }

    // ---- epilogue: normalize, pack single fp16 ctx --------------------------
    const float inv_a = 1.0f / l_a, inv_b = 1.0f / l_b;
    const int row_a = q0 + w * 16 + (lane >> 2);
    const int col0  = (lane & 3) * 2;
    #pragma unroll
    for (int nb = 0; nb < 8; nb++) {
        int col = nb * 8 + col0;
        size_t ea = base + (size_t)row_a * DMODEL + col;
        size_t eb = base + (size_t)(row_a + 8) * DMODEL + col;
        *(uint32_t*)(g_C + ea) = pack2h(o[nb][0] * inv_a, o[nb][1] * inv_a);
        *(uint32_t*)(g_C + eb) = pack2h(o[nb][2] * inv_b, o[nb][3] * inv_b);
    }
}

// ---------------------------------------------------------------------------
extern "C" void kernel_launch(void* const* d_in, const int* in_sizes, int n_in,
                              void* d_out, int out_size)
{
    const float* x  = (const float*)d_in[0];
    const float* Wq = (const float*)d_in[1];
    const float* bq = (const float*)d_in[2];
    const float* Wk = (const float*)d_in[3];
    const float* bk = (const float*)d_in[4];
    const float* Wv = (const float*)d_in[5];
    const float* bv = (const float*)d_in[6];
    const float* Wo = (const float*)d_in[7];
    const float* bo = (const float*)d_in[8];
    float* out = (float*)d_out;

    cudaFuncSetAttribute(gemm_qkv_mma,   cudaFuncAttributeMaxDynamicSharedMemorySize, SMEM_GEMM);
    cudaFuncSetAttribute(gemm_out_mma,   cudaFuncAttributeMaxDynamicSharedMemorySize, SMEM_GEMM);
    cudaFuncSetAttribute(flash_attn_mma, cudaFuncAttributeMaxDynamicSharedMemorySize, SMEM_FLASH);

    split_all<<<(XN8 + 4 * WN8) / 256, 256>>>(x, Wq, Wk, Wv, Wo);

    dim3 qgrid(DMODEL / 128, MTOT / 128, 3);
    gemm_qkv_mma<<<qgrid, 256, SMEM_GEMM>>>(bq, bk, bv);

    dim3 fgrid(SEQ / 128, NHEADS, BATCH);
    flash_attn_mma<<<fgrid, 256, SMEM_FLASH>>>();

    dim3 ogrid(DMODEL / 128, MTOT / 128, 1);
    gemm_out_mma<<<ogrid, 256, SMEM_GEMM>>>(bo, out);
}

// round 16
// speedup vs baseline: 1.0486x; 1.0486x over previous
#include <cuda_runtime.h>
#include <cuda_fp16.h>
#include <math_constants.h>
#include <cstdint>

#define BATCH  2
#define SEQ    2048
#define DMODEL 1024
#define NHEADS 16
#define HDIM   64
#define MTOT   (BATCH*SEQ)   // 4096
#define WSZ    (DMODEL*DMODEL)

// ---------------- scratch (allocation-free rule: __device__ globals) --------
__device__ __half g_X[(size_t)MTOT * DMODEL];
__device__ __half g_W[(size_t)4 * WSZ];
__device__ __half g_Q[(size_t)MTOT * DMODEL];
__device__ __half g_K[(size_t)MTOT * DMODEL];
__device__ __half g_V[(size_t)MTOT * DMODEL];
__device__ __half g_C[(size_t)MTOT * DMODEL];

// ---------------- helpers (baseline ISA only) --------------------------------
__device__ __forceinline__ uint32_t smem_u32(const void* p) {
    uint32_t a;
    asm("{ .reg .u64 t; cvta.to.shared.u64 t, %1; cvt.u32.u64 %0, t; }"
        : "=r"(a) : "l"(p));
    return a;
}
__device__ __forceinline__ void cpasync16(uint32_t dst, const void* src) {
    asm volatile("cp.async.cg.shared.global [%0], [%1], 16;" :: "r"(dst), "l"(src));
}
#define CPASYNC_COMMIT() asm volatile("cp.async.commit_group;" ::: "memory")
#define CPASYNC_WAIT(n)  asm volatile("cp.async.wait_group %0;" :: "n"(n) : "memory")

__device__ __forceinline__ void ldm_x4(uint32_t* r, uint32_t addr) {
    asm volatile("ldmatrix.sync.aligned.m8n8.x4.shared.b16 {%0,%1,%2,%3}, [%4];"
        : "=r"(r[0]), "=r"(r[1]), "=r"(r[2]), "=r"(r[3]) : "r"(addr));
}
__device__ __forceinline__ void ldm_x4t(uint32_t* r, uint32_t addr) {
    asm volatile("ldmatrix.sync.aligned.m8n8.x4.trans.shared.b16 {%0,%1,%2,%3}, [%4];"
        : "=r"(r[0]), "=r"(r[1]), "=r"(r[2]), "=r"(r[3]) : "r"(addr));
}
__device__ __forceinline__ void mma_f16(float* c, const uint32_t* a,
                                        uint32_t b0, uint32_t b1) {
    asm volatile("mma.sync.aligned.m16n8k16.row.col.f32.f16.f16.f32 "
        "{%0,%1,%2,%3}, {%4,%5,%6,%7}, {%8,%9}, {%0,%1,%2,%3};"
        : "+f"(c[0]), "+f"(c[1]), "+f"(c[2]), "+f"(c[3])
        : "r"(a[0]), "r"(a[1]), "r"(a[2]), "r"(a[3]), "r"(b0), "r"(b1));
}
__device__ __forceinline__ uint32_t pack2h(float v0, float v1) {
    __half h0 = __float2half_rn(v0), h1 = __float2half_rn(v1);
    return ((uint32_t)__half_as_ushort(h1) << 16) | __half_as_ushort(h0);
}

// ---------------- fused fp32 -> fp16 convert (x + 4 weights) -----------------
#define XN8  (MTOT * DMODEL / 8)          // 524288
#define WN8  (WSZ / 8)                    // 131072
__global__ __launch_bounds__(256)
void split_all(const float* __restrict__ x,  const float* __restrict__ Wq,
               const float* __restrict__ Wk, const float* __restrict__ Wv,
               const float* __restrict__ Wo)
{
    int id = blockIdx.x * 256 + threadIdx.x;
    const float* src;
    __half* dst;
    int off;
    if (id < XN8) {
        src = x; dst = g_X; off = id;
    } else {
        int r = (id - XN8) >> 17;          // WN8 = 2^17
        off   = (id - XN8) & (WN8 - 1);
        src = (r == 0) ? Wq : (r == 1) ? Wk : (r == 2) ? Wv : Wo;
        dst = g_W + (size_t)r * WSZ;
    }
    const float4* s = (const float4*)src + (size_t)off * 2;
    float4 a = s[0], b = s[1];
    uint4 hp;
    hp.x = pack2h(a.x, a.y);
    hp.y = pack2h(a.z, a.w);
    hp.z = pack2h(b.x, b.y);
    hp.w = pack2h(b.z, b.w);
    ((uint4*)dst)[off] = hp;
}

// ---------------- HMMA GEMM (256 thr, warp 64x32, BK=64, 3-stage) ------------
#define BK        64
#define ROWB      144                      // 128B data + 16B pad (conflict-free)
#define TILE_B    (128 * ROWB)             // 18432
#define OFF_B     (TILE_B)
#define STAGE_B   (2 * TILE_B)             // 36864
#define SMEM_GEMM (3 * STAGE_B)            // 110592

__device__ __forceinline__ void load_chunk(
    uint32_t sdst, const __half* __restrict__ A, const __half* __restrict__ W,
    int bm, int bn, int k0, int tid)
{
    #pragma unroll
    for (int it = 0; it < 4; it++) {
        int u = tid + it * 256;            // 0..1023: 128 rows x 8 x 16B
        int r = u >> 3, c = u & 7;
        uint32_t so = (uint32_t)(r * ROWB + c * 16);
        cpasync16(sdst + so,         A + (size_t)(bm + r) * DMODEL + k0 + c * 8);
        cpasync16(sdst + OFF_B + so, W + (size_t)(bn + r) * DMODEL + k0 + c * 8);
    }
}

__device__ __forceinline__ void gemm_hmma_body(
    const __half* __restrict__ A, const __half* __restrict__ W,
    const float* __restrict__ bias, int outmode,
    float* __restrict__ Y, __half* __restrict__ Yh)
{
    extern __shared__ char smem[];
    const uint32_t sb = smem_u32(smem);
    const int tid  = threadIdx.x;
    const int lane = tid & 31;
    const int wid  = tid >> 5;
    const int wm   = wid & 1;
    const int wn   = wid >> 1;

    const int bm = blockIdx.y * 128;
    const int bn = blockIdx.x * 128;

    float acc[4][4][4];
    #pragma unroll
    for (int mi = 0; mi < 4; mi++)
        #pragma unroll
        for (int ni = 0; ni < 4; ni++)
            #pragma unroll
            for (int e = 0; e < 4; e++) acc[mi][ni][e] = 0.f;

    const uint32_t a_row  = (uint32_t)(wm * 64 + (lane & 15));
    const uint32_t a_koff = (uint32_t)(((lane >> 4) & 1) * 16);
    const uint32_t b_nrow = (uint32_t)(wn * 32 + (lane & 7) + ((lane >> 4) & 1) * 8);
    const uint32_t b_koff = (uint32_t)(((lane >> 3) & 1) * 16);

    load_chunk(sb,           A, W, bm, bn, 0,  tid);
    CPASYNC_COMMIT();
    load_chunk(sb + STAGE_B, A, W, bm, bn, BK, tid);
    CPASYNC_COMMIT();

    const int NCH = DMODEL / BK;           // 16
    uint32_t stage = 0;
    for (int ch = 0; ch < NCH; ch++) {
        if (ch == NCH - 1) { CPASYNC_WAIT(0); } else { CPASYNC_WAIT(1); }
        __syncthreads();

        const uint32_t st = sb + stage;

        // ks = 0 first: let the first MMA wave start before issuing prefetch
        #pragma unroll
        for (int ks = 0; ks < 4; ks++) {
            const uint32_t kb = (uint32_t)(ks * 32);
            uint32_t aA[4][4], bB[2][4];
            #pragma unroll
            for (int mi = 0; mi < 4; mi++)
                ldm_x4(aA[mi], st + (a_row + mi * 16) * ROWB + kb + a_koff);
            #pragma unroll
            for (int p = 0; p < 2; p++)
                ldm_x4(bB[p], st + OFF_B + (b_nrow + p * 16) * ROWB + kb + b_koff);
            #pragma unroll
            for (int mi = 0; mi < 4; mi++)
                #pragma unroll
                for (int ni = 0; ni < 4; ni++) {
                    const uint32_t* bb = &bB[ni >> 1][(ni & 1) * 2];
                    mma_f16(acc[mi][ni], aA[mi], bb[0], bb[1]);
                }
            // issue the chunk+2 prefetch after the first sub-step's MMAs
            if (ks == 0 && ch + 2 < NCH) {
                uint32_t s2 = stage + 2 * STAGE_B;
                if (s2 >= 3 * STAGE_B) s2 -= 3 * STAGE_B;
                load_chunk(sb + s2, A, W, bm, bn, (ch + 2) * BK, tid);
                CPASYNC_COMMIT();
            }
        }
        stage += STAGE_B;
        if (stage >= 3 * STAGE_B) stage = 0;
    }

    const int l4 = lane >> 2;
    const int l2 = (lane & 3) * 2;
    #pragma unroll
    for (int mi = 0; mi < 4; mi++) {
        #pragma unroll
        for (int ni = 0; ni < 4; ni++) {
            int gr = bm + wm * 64 + mi * 16 + l4;
            int gc = bn + wn * 32 + ni * 8 + l2;
            float b0 = bias[gc], b1 = bias[gc + 1];
            float v0 = acc[mi][ni][0] + b0, v1 = acc[mi][ni][1] + b1;
            float v2 = acc[mi][ni][2] + b0, v3 = acc[mi][ni][3] + b1;
            if (outmode == 0) {
                *(float2*)(Y + (size_t)gr * DMODEL + gc)       = make_float2(v0, v1);
                *(float2*)(Y + (size_t)(gr + 8) * DMODEL + gc) = make_float2(v2, v3);
            } else {
                *(uint32_t*)(Yh + (size_t)gr * DMODEL + gc)       = pack2h(v0, v1);
                *(uint32_t*)(Yh + (size_t)(gr + 8) * DMODEL + gc) = pack2h(v2, v3);
            }
        }
    }
}

__global__ __launch_bounds__(256, 2)
void gemm_qkv_mma(const float* __restrict__ bq, const float* __restrict__ bk,
                  const float* __restrict__ bv)
{
    int z = blockIdx.z;
    const float* bias = (z == 0) ? bq : (z == 1) ? bk : bv;
    __half* Yh = (z == 0) ? g_Q : (z == 1) ? g_K : g_V;
    gemm_hmma_body(g_X, g_W + (size_t)z * WSZ, bias, 2, nullptr, Yh);
}

__global__ __launch_bounds__(256, 2)
void gemm_out_mma(const float* __restrict__ bo, float* __restrict__ Y)
{
    gemm_hmma_body(g_C, g_W + (size_t)3 * WSZ, bo, 0, Y, nullptr);
}

// ---------------- flash attention: fp32-acc S (proven best), 3-stage ---------
#define FROWB   144                        // 64 fp16 = 128B + 16B pad
#define FQTILE  (128 * FROWB)              // 18432
#define KTILE   (64 * FROWB)               // 9216
#define KVSTAGE (2 * KTILE)                // 18432
#define FK      0
#define FV      (KTILE)
#define SMEM_FLASH (FQTILE + 3 * KVSTAGE)  // 73728 (72 KB)

__device__ __forceinline__ void flash_load_q(uint32_t sb, const __half* Qs,
                                             int q0, int tid)
{
    #pragma unroll
    for (int it = 0; it < 4; it++) {
        int u = tid + it * 256;           // 0..1023
        int r = u >> 3, c = u & 7;
        uint32_t so = (uint32_t)(r * FROWB + c * 16);
        cpasync16(sb + so, Qs + (size_t)(q0 + r) * DMODEL + c * 8);
    }
}
__device__ __forceinline__ void flash_load_kv(uint32_t stb,
    const __half* Ks, const __half* Vs, int k0, int tid)
{
    #pragma unroll
    for (int it = 0; it < 2; it++) {
        int u = tid + it * 256;           // 0..511
        int r = u >> 3, c = u & 7;
        uint32_t so = (uint32_t)(r * FROWB + c * 16);
        size_t ge = (size_t)(k0 + r) * DMODEL + c * 8;
        cpasync16(stb + FK + so, Ks + ge);
        cpasync16(stb + FV + so, Vs + ge);
    }
}

__global__ __launch_bounds__(256, 2)
void flash_attn_mma()
{
    extern __shared__ char smem[];
    const uint32_t sb = smem_u32(smem);
    const uint32_t kvb = sb + FQTILE;
    const int tid  = threadIdx.x;
    const int w    = tid >> 5;
    const int lane = tid & 31;

    const int b  = blockIdx.z;
    const int h  = blockIdx.y;
    const int q0 = blockIdx.x * 128;

    const size_t base = (size_t)b * SEQ * DMODEL + (size_t)h * HDIM;
    const __half* Qs = g_Q + base;
    const __half* Ks = g_K + base;
    const __half* Vs = g_V + base;

    const uint32_t qa = (uint32_t)((w * 16 + (lane & 15)) * FROWB
                      + ((lane >> 4) & 1) * 16);
    const uint32_t ka_row = (uint32_t)((lane & 7) + ((lane >> 4) & 1) * 8);
    const uint32_t ka_ko  = (uint32_t)(((lane >> 3) & 1) * 16);
    const uint32_t va_row = (uint32_t)(lane & 15);
    const uint32_t va_co  = (uint32_t)(((lane >> 4) & 1) * 16);

    float o[8][4];
    #pragma unroll
    for (int nb = 0; nb < 8; nb++)
        #pragma unroll
        for (int e = 0; e < 4; e++) o[nb][e] = 0.f;
    float m_a = -CUDART_INF_F, m_b = -CUDART_INF_F, l_a = 0.f, l_b = 0.f;

    uint32_t aQ[4][4];

    flash_load_q(sb, Qs, q0, tid);
    flash_load_kv(kvb, Ks, Vs, 0, tid);
    CPASYNC_COMMIT();
    flash_load_kv(kvb + KVSTAGE, Ks, Vs, 64, tid);
    CPASYNC_COMMIT();

    const int NKT = SEQ / 64;             // 32
    uint32_t stage = 0;
    for (int kt = 0; kt < NKT; kt++) {
        if (kt == NKT - 1) { CPASYNC_WAIT(0); } else { CPASYNC_WAIT(1); }
        __syncthreads();

        if (kt + 2 < NKT) {
            uint32_t s2 = stage + 2 * KVSTAGE;
            if (s2 >= 3 * KVSTAGE) s2 -= 3 * KVSTAGE;
            flash_load_kv(kvb + s2, Ks, Vs, (kt + 2) * 64, tid);
            CPASYNC_COMMIT();
        }

        const uint32_t st = kvb + stage;

        if (kt == 0) {
            #pragma unroll
            for (int k4 = 0; k4 < 4; k4++)
                ldm_x4(aQ[k4], sb + qa + k4 * 32);
        }

        // ---- S = Q K^T : single pass, fp32 acc -------------------------------
        float s[8][4];
        #pragma unroll
        for (int j = 0; j < 8; j++)
            #pragma unroll
            for (int e = 0; e < 4; e++) s[j][e] = 0.f;

        #pragma unroll
        for (int k4 = 0; k4 < 4; k4++) {
            uint32_t kS[4][4];
            #pragma unroll
            for (int nb = 0; nb < 4; nb++)
                ldm_x4(kS[nb], st + FK + (uint32_t)(nb * 16) * FROWB
                               + ka_row * FROWB + ka_ko + k4 * 32);
            #pragma unroll
            for (int nb = 0; nb < 4; nb++) {
                mma_f16(s[2*nb],   aQ[k4], kS[nb][0], kS[nb][1]);
                mma_f16(s[2*nb+1], aQ[k4], kS[nb][2], kS[nb][3]);
            }
        }

        // ---- online softmax (rows a = lane/4, b = lane/4+8) -----------------
        float mloc_a = -CUDART_INF_F, mloc_b = -CUDART_INF_F;
        #pragma unroll
        for (int j = 0; j < 8; j++) {
            s[j][0] *= 0.125f; s[j][1] *= 0.125f;
            s[j][2] *= 0.125f; s[j][3] *= 0.125f;
            mloc_a = fmaxf(mloc_a, fmaxf(s[j][0], s[j][1]));
            mloc_b = fmaxf(mloc_b, fmaxf(s[j][2], s[j][3]));
        }
        mloc_a = fmaxf(mloc_a, __shfl_xor_sync(0xffffffffu, mloc_a, 1));
        mloc_a = fmaxf(mloc_a, __shfl_xor_sync(0xffffffffu, mloc_a, 2));
        mloc_b = fmaxf(mloc_b, __shfl_xor_sync(0xffffffffu, mloc_b, 1));
        mloc_b = fmaxf(mloc_b, __shfl_xor_sync(0xffffffffu, mloc_b, 2));

        float mn_a = fmaxf(m_a, mloc_a), mn_b = fmaxf(m_b, mloc_b);
        float corr_a = __expf(m_a - mn_a), corr_b = __expf(m_b - mn_b);
        m_a = mn_a; m_b = mn_b;

        float rs_a = 0.f, rs_b = 0.f;
        #pragma unroll
        for (int j = 0; j < 8; j++) {
            s[j][0] = __expf(s[j][0] - mn_a);
            s[j][1] = __expf(s[j][1] - mn_a);
            s[j][2] = __expf(s[j][2] - mn_b);
            s[j][3] = __expf(s[j][3] - mn_b);
            rs_a += s[j][0] + s[j][1];
            rs_b += s[j][2] + s[j][3];
        }
        rs_a += __shfl_xor_sync(0xffffffffu, rs_a, 1);
        rs_a += __shfl_xor_sync(0xffffffffu, rs_a, 2);
        rs_b += __shfl_xor_sync(0xffffffffu, rs_b, 1);
        rs_b += __shfl_xor_sync(0xffffffffu, rs_b, 2);
        l_a = l_a * corr_a + rs_a;
        l_b = l_b * corr_b + rs_b;

        #pragma unroll
        for (int nb = 0; nb < 8; nb++) {
            o[nb][0] *= corr_a; o[nb][1] *= corr_a;
            o[nb][2] *= corr_b; o[nb][3] *= corr_b;
        }

        // ---- O += P V: single pass, fp32 acc ----------------------------------
        #pragma unroll
        for (int t = 0; t < 4; t++) {
            uint32_t pP[4];
            pP[0] = pack2h(s[2*t][0],   s[2*t][1]);
            pP[1] = pack2h(s[2*t][2],   s[2*t][3]);
            pP[2] = pack2h(s[2*t+1][0], s[2*t+1][1]);
            pP[3] = pack2h(s[2*t+1][2], s[2*t+1][3]);

            uint32_t vS[4][4];
            #pragma unroll
            for (int ng = 0; ng < 4; ng++)
                ldm_x4t(vS[ng], st + FV + (uint32_t)(t * 16 + va_row) * FROWB
                                + (uint32_t)(ng * 32) + va_co);
            #pragma unroll
            for (int ng = 0; ng < 4; ng++) {
                mma_f16(o[2*ng],   pP, vS[ng][0], vS[ng][1]);
                mma_f16(o[2*ng+1], pP, vS[ng][2], vS[ng][3]);
            }
        }
        stage += KVSTAGE;
        if (stage >= 3 * KVSTAGE) stage = 0;
    }

    // ---- epilogue: normalize, pack single fp16 ctx --------------------------
    const float inv_a = 1.0f / l_a, inv_b = 1.0f / l_b;
    const int row_a = q0 + w * 16 + (lane >> 2);
    const int col0  = (lane & 3) * 2;
    #pragma unroll
    for (int nb = 0; nb < 8; nb++) {
        int col = nb * 8 + col0;
        size_t ea = base + (size_t)row_a * DMODEL + col;
        size_t eb = base + (size_t)(row_a + 8) * DMODEL + col;
        *(uint32_t*)(g_C + ea) = pack2h(o[nb][0] * inv_a, o[nb][1] * inv_a);
        *(uint32_t*)(g_C + eb) = pack2h(o[nb][2] * inv_b, o[nb][3] * inv_b);
    }
}

// ---------------------------------------------------------------------------
extern "C" void kernel_launch(void* const* d_in, const int* in_sizes, int n_in,
                              void* d_out, int out_size)
{
    const float* x  = (const float*)d_in[0];
    const float* Wq = (const float*)d_in[1];
    const float* bq = (const float*)d_in[2];
    const float* Wk = (const float*)d_in[3];
    const float* bk = (const float*)d_in[4];
    const float* Wv = (const float*)d_in[5];
    const float* bv = (const float*)d_in[6];
    const float* Wo = (const float*)d_in[7];
    const float* bo = (const float*)d_in[8];
    float* out = (float*)d_out;

    cudaFuncSetAttribute(gemm_qkv_mma,   cudaFuncAttributeMaxDynamicSharedMemorySize, SMEM_GEMM);
    cudaFuncSetAttribute(gemm_out_mma,   cudaFuncAttributeMaxDynamicSharedMemorySize, SMEM_GEMM);
    cudaFuncSetAttribute(flash_attn_mma, cudaFuncAttributeMaxDynamicSharedMemorySize, SMEM_FLASH);

    split_all<<<(XN8 + 4 * WN8) / 256, 256>>>(x, Wq, Wk, Wv, Wo);

    dim3 qgrid(DMODEL / 128, MTOT / 128, 3);
    gemm_qkv_mma<<<qgrid, 256, SMEM_GEMM>>>(bq, bk, bv);

    dim3 fgrid(SEQ / 128, NHEADS, BATCH);
    flash_attn_mma<<<fgrid, 256, SMEM_FLASH>>>();

    dim3 ogrid(DMODEL / 128, MTOT / 128, 1);
    gemm_out_mma<<<ogrid, 256, SMEM_GEMM>>>(bo, out);
}

// round 17
// speedup vs baseline: 1.0909x; 1.0403x over previous
#include <cuda_runtime.h>
#include <cuda_fp16.h>
#include <math_constants.h>
#include <cstdint>

#define BATCH  2
#define SEQ    2048
#define DMODEL 1024
#define NHEADS 16
#define HDIM   64
#define MTOT   (BATCH*SEQ)   // 4096
#define WSZ    (DMODEL*DMODEL)

// ---------------- scratch (allocation-free rule: __device__ globals) --------
__device__ __half g_X[(size_t)MTOT * DMODEL];
__device__ __half g_W[(size_t)4 * WSZ];
__device__ __half g_Q[(size_t)MTOT * DMODEL];
__device__ __half g_K[(size_t)MTOT * DMODEL];
__device__ __half g_V[(size_t)MTOT * DMODEL];
__device__ __half g_C[(size_t)MTOT * DMODEL];

// ---------------- helpers (baseline ISA only) --------------------------------
__device__ __forceinline__ uint32_t smem_u32(const void* p) {
    uint32_t a;
    asm("{ .reg .u64 t; cvta.to.shared.u64 t, %1; cvt.u32.u64 %0, t; }"
        : "=r"(a) : "l"(p));
    return a;
}
__device__ __forceinline__ void cpasync16(uint32_t dst, const void* src) {
    asm volatile("cp.async.cg.shared.global [%0], [%1], 16;" :: "r"(dst), "l"(src));
}
#define CPASYNC_COMMIT() asm volatile("cp.async.commit_group;" ::: "memory")
#define CPASYNC_WAIT(n)  asm volatile("cp.async.wait_group %0;" :: "n"(n) : "memory")

__device__ __forceinline__ void ldm_x4(uint32_t* r, uint32_t addr) {
    asm volatile("ldmatrix.sync.aligned.m8n8.x4.shared.b16 {%0,%1,%2,%3}, [%4];"
        : "=r"(r[0]), "=r"(r[1]), "=r"(r[2]), "=r"(r[3]) : "r"(addr));
}
__device__ __forceinline__ void ldm_x4t(uint32_t* r, uint32_t addr) {
    asm volatile("ldmatrix.sync.aligned.m8n8.x4.trans.shared.b16 {%0,%1,%2,%3}, [%4];"
        : "=r"(r[0]), "=r"(r[1]), "=r"(r[2]), "=r"(r[3]) : "r"(addr));
}
__device__ __forceinline__ void mma_f16(float* c, const uint32_t* a,
                                        uint32_t b0, uint32_t b1) {
    asm volatile("mma.sync.aligned.m16n8k16.row.col.f32.f16.f16.f32 "
        "{%0,%1,%2,%3}, {%4,%5,%6,%7}, {%8,%9}, {%0,%1,%2,%3};"
        : "+f"(c[0]), "+f"(c[1]), "+f"(c[2]), "+f"(c[3])
        : "r"(a[0]), "r"(a[1]), "r"(a[2]), "r"(a[3]), "r"(b0), "r"(b1));
}
__device__ __forceinline__ uint32_t pack2h(float v0, float v1) {
    __half h0 = __float2half_rn(v0), h1 = __float2half_rn(v1);
    return ((uint32_t)__half_as_ushort(h1) << 16) | __half_as_ushort(h0);
}

// ---------------- fused fp32 -> fp16 convert (x + 4 weights) -----------------
#define XN8  (MTOT * DMODEL / 8)          // 524288
#define WN8  (WSZ / 8)                    // 131072
__global__ __launch_bounds__(256)
void split_all(const float* __restrict__ x,  const float* __restrict__ Wq,
               const float* __restrict__ Wk, const float* __restrict__ Wv,
               const float* __restrict__ Wo)
{
    int id = blockIdx.x * 256 + threadIdx.x;
    const float* src;
    __half* dst;
    int off;
    if (id < XN8) {
        src = x; dst = g_X; off = id;
    } else {
        int r = (id - XN8) >> 17;          // WN8 = 2^17
        off   = (id - XN8) & (WN8 - 1);
        src = (r == 0) ? Wq : (r == 1) ? Wk : (r == 2) ? Wv : Wo;
        dst = g_W + (size_t)r * WSZ;
    }
    const float4* s = (const float4*)src + (size_t)off * 2;
    float4 a = s[0], b = s[1];
    uint4 hp;
    hp.x = pack2h(a.x, a.y);
    hp.y = pack2h(a.z, a.w);
    hp.z = pack2h(b.x, b.y);
    hp.w = pack2h(b.z, b.w);
    ((uint4*)dst)[off] = hp;
}

// ---------------- HMMA GEMM (256 thr, warp 64x32, BK=64, 3-stage) ------------
#define BK        64
#define ROWB      144                      // 128B data + 16B pad (conflict-free)
#define TILE_B    (128 * ROWB)             // 18432
#define OFF_B     (TILE_B)
#define STAGE_B   (2 * TILE_B)             // 36864
#define SMEM_GEMM (3 * STAGE_B)            // 110592

__device__ __forceinline__ void load_chunk(
    uint32_t sdst, const __half* __restrict__ A, const __half* __restrict__ W,
    int bm, int bn, int k0, int tid)
{
    #pragma unroll
    for (int it = 0; it < 4; it++) {
        int u = tid + it * 256;            // 0..1023: 128 rows x 8 x 16B
        int r = u >> 3, c = u & 7;
        uint32_t so = (uint32_t)(r * ROWB + c * 16);
        cpasync16(sdst + so,         A + (size_t)(bm + r) * DMODEL + k0 + c * 8);
        cpasync16(sdst + OFF_B + so, W + (size_t)(bn + r) * DMODEL + k0 + c * 8);
    }
}

__device__ __forceinline__ void gemm_hmma_body(
    const __half* __restrict__ A, const __half* __restrict__ W,
    const float* __restrict__ bias, int outmode,
    float* __restrict__ Y, __half* __restrict__ Yh)
{
    extern __shared__ char smem[];
    const uint32_t sb = smem_u32(smem);
    const int tid  = threadIdx.x;
    const int lane = tid & 31;
    const int wid  = tid >> 5;
    const int wm   = wid & 1;
    const int wn   = wid >> 1;

    const int bm = blockIdx.y * 128;
    const int bn = blockIdx.x * 128;

    float acc[4][4][4];
    #pragma unroll
    for (int mi = 0; mi < 4; mi++)
        #pragma unroll
        for (int ni = 0; ni < 4; ni++)
            #pragma unroll
            for (int e = 0; e < 4; e++) acc[mi][ni][e] = 0.f;

    const uint32_t a_row  = (uint32_t)(wm * 64 + (lane & 15));
    const uint32_t a_koff = (uint32_t)(((lane >> 4) & 1) * 16);
    const uint32_t b_nrow = (uint32_t)(wn * 32 + (lane & 7) + ((lane >> 4) & 1) * 8);
    const uint32_t b_koff = (uint32_t)(((lane >> 3) & 1) * 16);

    load_chunk(sb,           A, W, bm, bn, 0,  tid);
    CPASYNC_COMMIT();
    load_chunk(sb + STAGE_B, A, W, bm, bn, BK, tid);
    CPASYNC_COMMIT();

    const int NCH = DMODEL / BK;           // 16
    uint32_t stage = 0;
    for (int ch = 0; ch < NCH; ch++) {
        if (ch == NCH - 1) { CPASYNC_WAIT(0); } else { CPASYNC_WAIT(1); }
        __syncthreads();

        const uint32_t st = sb + stage;

        #pragma unroll
        for (int ks = 0; ks < 4; ks++) {
            const uint32_t kb = (uint32_t)(ks * 32);
            uint32_t aA[4][4], bB[2][4];
            #pragma unroll
            for (int mi = 0; mi < 4; mi++)
                ldm_x4(aA[mi], st + (a_row + mi * 16) * ROWB + kb + a_koff);
            #pragma unroll
            for (int p = 0; p < 2; p++)
                ldm_x4(bB[p], st + OFF_B + (b_nrow + p * 16) * ROWB + kb + b_koff);
            #pragma unroll
            for (int mi = 0; mi < 4; mi++)
                #pragma unroll
                for (int ni = 0; ni < 4; ni++) {
                    const uint32_t* bb = &bB[ni >> 1][(ni & 1) * 2];
                    mma_f16(acc[mi][ni], aA[mi], bb[0], bb[1]);
                }
            if (ks == 0 && ch + 2 < NCH) {
                uint32_t s2 = stage + 2 * STAGE_B;
                if (s2 >= 3 * STAGE_B) s2 -= 3 * STAGE_B;
                load_chunk(sb + s2, A, W, bm, bn, (ch + 2) * BK, tid);
                CPASYNC_COMMIT();
            }
        }
        stage += STAGE_B;
        if (stage >= 3 * STAGE_B) stage = 0;
    }

    const int l4 = lane >> 2;
    const int l2 = (lane & 3) * 2;
    #pragma unroll
    for (int mi = 0; mi < 4; mi++) {
        #pragma unroll
        for (int ni = 0; ni < 4; ni++) {
            int gr = bm + wm * 64 + mi * 16 + l4;
            int gc = bn + wn * 32 + ni * 8 + l2;
            float b0 = bias[gc], b1 = bias[gc + 1];
            float v0 = acc[mi][ni][0] + b0, v1 = acc[mi][ni][1] + b1;
            float v2 = acc[mi][ni][2] + b0, v3 = acc[mi][ni][3] + b1;
            if (outmode == 0) {
                *(float2*)(Y + (size_t)gr * DMODEL + gc)       = make_float2(v0, v1);
                *(float2*)(Y + (size_t)(gr + 8) * DMODEL + gc) = make_float2(v2, v3);
            } else {
                *(uint32_t*)(Yh + (size_t)gr * DMODEL + gc)       = pack2h(v0, v1);
                *(uint32_t*)(Yh + (size_t)(gr + 8) * DMODEL + gc) = pack2h(v2, v3);
            }
        }
    }
}

__global__ __launch_bounds__(256, 2)
void gemm_qkv_mma(const float* __restrict__ bq, const float* __restrict__ bk,
                  const float* __restrict__ bv)
{
    int z = blockIdx.z;
    const float* bias = (z == 0) ? bq : (z == 1) ? bk : bv;
    __half* Yh = (z == 0) ? g_Q : (z == 1) ? g_K : g_V;
    gemm_hmma_body(g_X, g_W + (size_t)z * WSZ, bias, 2, nullptr, Yh);
}

__global__ __launch_bounds__(256, 2)
void gemm_out_mma(const float* __restrict__ bo, float* __restrict__ Y)
{
    gemm_hmma_body(g_C, g_W + (size_t)3 * WSZ, bo, 0, Y, nullptr);
}

// ---------------- flash attention: fp32-acc, deferred KV prefetch ------------
#define FROWB   144                        // 64 fp16 = 128B + 16B pad
#define FQTILE  (128 * FROWB)              // 18432
#define KTILE   (64 * FROWB)               // 9216
#define KVSTAGE (2 * KTILE)                // 18432
#define FK      0
#define FV      (KTILE)
#define SMEM_FLASH (FQTILE + 3 * KVSTAGE)  // 73728 (72 KB)

__device__ __forceinline__ void flash_load_q(uint32_t sb, const __half* Qs,
                                             int q0, int tid)
{
    #pragma unroll
    for (int it = 0; it < 4; it++) {
        int u = tid + it * 256;           // 0..1023
        int r = u >> 3, c = u & 7;
        uint32_t so = (uint32_t)(r * FROWB + c * 16);
        cpasync16(sb + so, Qs + (size_t)(q0 + r) * DMODEL + c * 8);
    }
}
__device__ __forceinline__ void flash_load_kv(uint32_t stb,
    const __half* Ks, const __half* Vs, int k0, int tid)
{
    #pragma unroll
    for (int it = 0; it < 2; it++) {
        int u = tid + it * 256;           // 0..511
        int r = u >> 3, c = u & 7;
        uint32_t so = (uint32_t)(r * FROWB + c * 16);
        size_t ge = (size_t)(k0 + r) * DMODEL + c * 8;
        cpasync16(stb + FK + so, Ks + ge);
        cpasync16(stb + FV + so, Vs + ge);
    }
}

__global__ __launch_bounds__(256, 2)
void flash_attn_mma()
{
    extern __shared__ char smem[];
    const uint32_t sb = smem_u32(smem);
    const uint32_t kvb = sb + FQTILE;
    const int tid  = threadIdx.x;
    const int w    = tid >> 5;
    const int lane = tid & 31;

    const int b  = blockIdx.z;
    const int h  = blockIdx.y;
    const int q0 = blockIdx.x * 128;

    const size_t base = (size_t)b * SEQ * DMODEL + (size_t)h * HDIM;
    const __half* Qs = g_Q + base;
    const __half* Ks = g_K + base;
    const __half* Vs = g_V + base;

    const uint32_t qa = (uint32_t)((w * 16 + (lane & 15)) * FROWB
                      + ((lane >> 4) & 1) * 16);
    const uint32_t ka_row = (uint32_t)((lane & 7) + ((lane >> 4) & 1) * 8);
    const uint32_t ka_ko  = (uint32_t)(((lane >> 3) & 1) * 16);
    const uint32_t va_row = (uint32_t)(lane & 15);
    const uint32_t va_co  = (uint32_t)(((lane >> 4) & 1) * 16);

    float o[8][4];
    #pragma unroll
    for (int nb = 0; nb < 8; nb++)
        #pragma unroll
        for (int e = 0; e < 4; e++) o[nb][e] = 0.f;
    float m_a = -CUDART_INF_F, m_b = -CUDART_INF_F, l_a = 0.f, l_b = 0.f;

    uint32_t aQ[4][4];

    flash_load_q(sb, Qs, q0, tid);
    flash_load_kv(kvb, Ks, Vs, 0, tid);
    CPASYNC_COMMIT();
    flash_load_kv(kvb + KVSTAGE, Ks, Vs, 64, tid);
    CPASYNC_COMMIT();

    const int NKT = SEQ / 64;             // 32
    uint32_t stage = 0;
    for (int kt = 0; kt < NKT; kt++) {
        if (kt == NKT - 1) { CPASYNC_WAIT(0); } else { CPASYNC_WAIT(1); }
        __syncthreads();

        const uint32_t st = kvb + stage;

        if (kt == 0) {
            #pragma unroll
            for (int k4 = 0; k4 < 4; k4++)
                ldm_x4(aQ[k4], sb + qa + k4 * 32);
        }

        // ---- S = Q K^T : single pass, fp32 acc -------------------------------
        float s[8][4];
        #pragma unroll
        for (int j = 0; j < 8; j++)
            #pragma unroll
            for (int e = 0; e < 4; e++) s[j][e] = 0.f;

        #pragma unroll
        for (int k4 = 0; k4 < 4; k4++) {
            uint32_t kS[4][4];
            #pragma unroll
            for (int nb = 0; nb < 4; nb++)
                ldm_x4(kS[nb], st + FK + (uint32_t)(nb * 16) * FROWB
                               + ka_row * FROWB + ka_ko + k4 * 32);
            #pragma unroll
            for (int nb = 0; nb < 4; nb++) {
                mma_f16(s[2*nb],   aQ[k4], kS[nb][0], kS[nb][1]);
                mma_f16(s[2*nb+1], aQ[k4], kS[nb][2], kS[nb][3]);
            }
        }

        // ---- deferred KV prefetch: issue after S's LDSM burst ----------------
        if (kt + 2 < NKT) {
            uint32_t s2 = stage + 2 * KVSTAGE;
            if (s2 >= 3 * KVSTAGE) s2 -= 3 * KVSTAGE;
            flash_load_kv(kvb + s2, Ks, Vs, (kt + 2) * 64, tid);
            CPASYNC_COMMIT();
        }

        // ---- online softmax (rows a = lane/4, b = lane/4+8) -----------------
        float mloc_a = -CUDART_INF_F, mloc_b = -CUDART_INF_F;
        #pragma unroll
        for (int j = 0; j < 8; j++) {
            s[j][0] *= 0.125f; s[j][1] *= 0.125f;
            s[j][2] *= 0.125f; s[j][3] *= 0.125f;
            mloc_a = fmaxf(mloc_a, fmaxf(s[j][0], s[j][1]));
            mloc_b = fmaxf(mloc_b, fmaxf(s[j][2], s[j][3]));
        }
        mloc_a = fmaxf(mloc_a, __shfl_xor_sync(0xffffffffu, mloc_a, 1));
        mloc_a = fmaxf(mloc_a, __shfl_xor_sync(0xffffffffu, mloc_a, 2));
        mloc_b = fmaxf(mloc_b, __shfl_xor_sync(0xffffffffu, mloc_b, 1));
        mloc_b = fmaxf(mloc_b, __shfl_xor_sync(0xffffffffu, mloc_b, 2));

        float mn_a = fmaxf(m_a, mloc_a), mn_b = fmaxf(m_b, mloc_b);
        float corr_a = __expf(m_a - mn_a), corr_b = __expf(m_b - mn_b);
        m_a = mn_a; m_b = mn_b;

        float rs_a = 0.f, rs_b = 0.f;
        #pragma unroll
        for (int j = 0; j < 8; j++) {
            s[j][0] = __expf(s[j][0] - mn_a);
            s[j][1] = __expf(s[j][1] - mn_a);
            s[j][2] = __expf(s[j][2] - mn_b);
            s[j][3] = __expf(s[j][3] - mn_b);
            rs_a += s[j][0] + s[j][1];
            rs_b += s[j][2] + s[j][3];
        }
        rs_a += __shfl_xor_sync(0xffffffffu, rs_a, 1);
        rs_a += __shfl_xor_sync(0xffffffffu, rs_a, 2);
        rs_b += __shfl_xor_sync(0xffffffffu, rs_b, 1);
        rs_b += __shfl_xor_sync(0xffffffffu, rs_b, 2);
        l_a = l_a * corr_a + rs_a;
        l_b = l_b * corr_b + rs_b;

        #pragma unroll
        for (int nb = 0; nb < 8; nb++) {
            o[nb][0] *= corr_a; o[nb][1] *= corr_a;
            o[nb][2] *= corr_b; o[nb][3] *= corr_b;
        }

        // ---- O += P V: single pass, fp32 acc ----------------------------------
        #pragma unroll
        for (int t = 0; t < 4; t++) {
            uint32_t pP[4];
            pP[0] = pack2h(s[2*t][0],   s[2*t][1]);
            pP[1] = pack2h(s[2*t][2],   s[2*t][3]);
            pP[2] = pack2h(s[2*t+1][0], s[2*t+1][1]);
            pP[3] = pack2h(s[2*t+1][2], s[2*t+1][3]);

            uint32_t vS[4][4];
            #pragma unroll
            for (int ng = 0; ng < 4; ng++)
                ldm_x4t(vS[ng], st + FV + (uint32_t)(t * 16 + va_row) * FROWB
                                + (uint32_t)(ng * 32) + va_co);
            #pragma unroll
            for (int ng = 0; ng < 4; ng++) {
                mma_f16(o[2*ng],   pP, vS[ng][0], vS[ng][1]);
                mma_f16(o[2*ng+1], pP, vS[ng][2], vS[ng][3]);
            }
        }
        stage += KVSTAGE;
        if (stage >= 3 * KVSTAGE) stage = 0;
    }

    // ---- epilogue: normalize, pack single fp16 ctx --------------------------
    const float inv_a = 1.0f / l_a, inv_b = 1.0f / l_b;
    const int row_a = q0 + w * 16 + (lane >> 2);
    const int col0  = (lane & 3) * 2;
    #pragma unroll
    for (int nb = 0; nb < 8; nb++) {
        int col = nb * 8 + col0;
        size_t ea = base + (size_t)row_a * DMODEL + col;
        size_t eb = base + (size_t)(row_a + 8) * DMODEL + col;
        *(uint32_t*)(g_C + ea) = pack2h(o[nb][0] * inv_a, o[nb][1] * inv_a);
        *(uint32_t*)(g_C + eb) = pack2h(o[nb][2] * inv_b, o[nb][3] * inv_b);
    }
}

// ---------------------------------------------------------------------------
extern "C" void kernel_launch(void* const* d_in, const int* in_sizes, int n_in,
                              void* d_out, int out_size)
{
    const float* x  = (const float*)d_in[0];
    const float* Wq = (const float*)d_in[1];
    const float* bq = (const float*)d_in[2];
    const float* Wk = (const float*)d_in[3];
    const float* bk = (const float*)d_in[4];
    const float* Wv = (const float*)d_in[5];
    const float* bv = (const float*)d_in[6];
    const float* Wo = (const float*)d_in[7];
    const float* bo = (const float*)d_in[8];
    float* out = (float*)d_out;

    cudaFuncSetAttribute(gemm_qkv_mma,   cudaFuncAttributeMaxDynamicSharedMemorySize, SMEM_GEMM);
    cudaFuncSetAttribute(gemm_out_mma,   cudaFuncAttributeMaxDynamicSharedMemorySize, SMEM_GEMM);
    cudaFuncSetAttribute(flash_attn_mma, cudaFuncAttributeMaxDynamicSharedMemorySize, SMEM_FLASH);

    split_all<<<(XN8 + 4 * WN8) / 256, 256>>>(x, Wq, Wk, Wv, Wo);

    dim3 qgrid(DMODEL / 128, MTOT / 128, 3);
    gemm_qkv_mma<<<qgrid, 256, SMEM_GEMM>>>(bq, bk, bv);

    dim3 fgrid(SEQ / 128, NHEADS, BATCH);
    flash_attn_mma<<<fgrid, 256, SMEM_FLASH>>>();

    dim3 ogrid(DMODEL / 128, MTOT / 128, 1);
    gemm_out_mma<<<ogrid, 256, SMEM_GEMM>>>(bo, out);
}